// round 1
// baseline (speedup 1.0000x reference)
#include <cuda_runtime.h>
#include <math.h>

// ---------------- problem constants ----------------
#define BB   8
#define SS   577
#define DD   768
#define HH   12
#define HDIM 64
#define PP   576
#define KWIN 32
#define MLPD 3072
#define NROWS (BB*SS)        // 4616
#define SCALE_ATT 0.125f     // 64^-0.5
#define TEMP_INV  10.0f

// ---------------- scratch (device globals, no allocation) ----------------
__device__ float g_xn   [(size_t)BB*SS*DD];
__device__ float g_q    [(size_t)BB*PP*DD];
__device__ float g_k    [(size_t)BB*PP*DD];
__device__ float g_scores[(size_t)BB*PP*PP];
__device__ int   g_routes[(size_t)BB*PP*KWIN];
__device__ float g_logw  [(size_t)BB*PP*KWIN];
__device__ float g_qkv  [(size_t)BB*SS*3*DD];
__device__ float g_attn [(size_t)BB*SS*DD];
__device__ float g_x1   [(size_t)BB*SS*DD];
__device__ float g_xn2  [(size_t)BB*SS*DD];
__device__ float g_h    [(size_t)BB*SS*MLPD];

// ---------------- LayerNorm ----------------
__global__ __launch_bounds__(256) void ln_kernel(
    const float* __restrict__ x, const float* __restrict__ g,
    const float* __restrict__ b, float* __restrict__ y)
{
    int row = blockIdx.x;
    const float* xr = x + (long)row*DD;
    float s = 0.f, sq = 0.f;
    for (int d = threadIdx.x; d < DD; d += 256) {
        float v = xr[d]; s += v; sq += v*v;
    }
    __shared__ float rs[256], rq[256];
    rs[threadIdx.x] = s; rq[threadIdx.x] = sq;
    __syncthreads();
    for (int o = 128; o > 0; o >>= 1) {
        if (threadIdx.x < o) { rs[threadIdx.x] += rs[threadIdx.x+o]; rq[threadIdx.x] += rq[threadIdx.x+o]; }
        __syncthreads();
    }
    __shared__ float mean_s, rstd_s;
    if (threadIdx.x == 0) {
        float mean = rs[0] / (float)DD;
        float var  = rq[0] / (float)DD - mean*mean;
        mean_s = mean;
        rstd_s = rsqrtf(var + 1e-5f);
    }
    __syncthreads();
    float mean = mean_s, rstd = rstd_s;
    float* yr = y + (long)row*DD;
    for (int d = threadIdx.x; d < DD; d += 256)
        yr[d] = (xr[d]-mean)*rstd*g[d] + b[d];
}

// ---------------- L2 normalize rows (in place) ----------------
__global__ __launch_bounds__(256) void l2norm_kernel(float* __restrict__ x)
{
    int row = blockIdx.x;
    float* xr = x + (long)row*DD;
    float sq = 0.f;
    for (int d = threadIdx.x; d < DD; d += 256) { float v = xr[d]; sq += v*v; }
    __shared__ float rq[256];
    rq[threadIdx.x] = sq;
    __syncthreads();
    for (int o = 128; o > 0; o >>= 1) {
        if (threadIdx.x < o) rq[threadIdx.x] += rq[threadIdx.x+o];
        __syncthreads();
    }
    __shared__ float inv_s;
    if (threadIdx.x == 0) {
        float nrm = sqrtf(rq[0]);
        inv_s = 1.0f / fmaxf(nrm, 1e-12f);
    }
    __syncthreads();
    float inv = inv_s;
    for (int d = threadIdx.x; d < DD; d += 256) xr[d] *= inv;
}

// ---------------- SGEMM 128x128x16, 8x8/thread ----------------
// EPI: 0 = +bias ; 1 = scores (+pos_bias, diag mask, *1/TEMP) ;
//      2 = +bias +residual ; 3 = +bias, exact GELU
template<int EPI, int TRANSB>
__global__ __launch_bounds__(256) void sgemm_kernel(
    const float* __restrict__ A, const float* __restrict__ Bm,
    float* __restrict__ C, int M, int N, int K,
    long sA, long sB, long sC,
    const float* __restrict__ bias,
    const float* __restrict__ extra, long sE)
{
    const int BM = 128, BN = 128, BK = 16;
    __shared__ float As[BK][BM+4];
    __shared__ float Bs[BK][BN+4];

    int bz = blockIdx.z;
    A  += bz*sA;
    Bm += bz*sB;
    C  += bz*sC;
    const float* Ex = extra ? (extra + bz*sE) : nullptr;

    int bm = blockIdx.y * BM;
    int bn = blockIdx.x * BN;
    int tid = threadIdx.x;
    int tx = tid & 15, ty = tid >> 4;

    float acc[8][8];
    #pragma unroll
    for (int i = 0; i < 8; i++)
        #pragma unroll
        for (int j = 0; j < 8; j++) acc[i][j] = 0.f;

    int a_r = tid >> 2;          // 0..63
    int a_c = (tid & 3) * 4;     // 0,4,8,12
    int b_r = tid >> 5;          // 0..7  (NN loads)
    int b_c = (tid & 31) * 4;    // 0..124

    for (int k0 = 0; k0 < K; k0 += BK) {
        // A tile (transposed into SMEM)
        #pragma unroll
        for (int pp = 0; pp < 2; pp++) {
            int m = bm + a_r + pp*64;
            float4 v = make_float4(0.f,0.f,0.f,0.f);
            if (m < M) v = *reinterpret_cast<const float4*>(A + (long)m*K + k0 + a_c);
            As[a_c+0][a_r+pp*64] = v.x;
            As[a_c+1][a_r+pp*64] = v.y;
            As[a_c+2][a_r+pp*64] = v.z;
            As[a_c+3][a_r+pp*64] = v.w;
        }
        if (TRANSB) {   // B is [N,K] row-major
            #pragma unroll
            for (int pp = 0; pp < 2; pp++) {
                int n = bn + a_r + pp*64;
                float4 v = make_float4(0.f,0.f,0.f,0.f);
                if (n < N) v = *reinterpret_cast<const float4*>(Bm + (long)n*K + k0 + a_c);
                Bs[a_c+0][a_r+pp*64] = v.x;
                Bs[a_c+1][a_r+pp*64] = v.y;
                Bs[a_c+2][a_r+pp*64] = v.z;
                Bs[a_c+3][a_r+pp*64] = v.w;
            }
        } else {        // B is [K,N] row-major
            #pragma unroll
            for (int pp = 0; pp < 2; pp++) {
                int kk = k0 + b_r + pp*8;
                int n  = bn + b_c;
                float4 v = make_float4(0.f,0.f,0.f,0.f);
                if (n < N) v = *reinterpret_cast<const float4*>(Bm + (long)kk*N + n);
                *reinterpret_cast<float4*>(&Bs[b_r+pp*8][b_c]) = v;
            }
        }
        __syncthreads();

        #pragma unroll
        for (int kk = 0; kk < BK; kk++) {
            float a[8], bfrag[8];
            #pragma unroll
            for (int i = 0; i < 4; i++) {
                a[i]       = As[kk][ty*4+i];
                a[i+4]     = As[kk][64+ty*4+i];
                bfrag[i]   = Bs[kk][tx*4+i];
                bfrag[i+4] = Bs[kk][64+tx*4+i];
            }
            #pragma unroll
            for (int i = 0; i < 8; i++)
                #pragma unroll
                for (int j = 0; j < 8; j++)
                    acc[i][j] = fmaf(a[i], bfrag[j], acc[i][j]);
        }
        __syncthreads();
    }

    #pragma unroll
    for (int i = 0; i < 8; i++) {
        int m = bm + ((i < 4) ? (ty*4+i) : (64+ty*4+(i-4)));
        if (m >= M) continue;
        #pragma unroll
        for (int j = 0; j < 8; j++) {
            int n = bn + ((j < 4) ? (tx*4+j) : (64+tx*4+(j-4)));
            if (n >= N) continue;
            float v = acc[i][j];
            if (EPI == 0 || EPI == 2 || EPI == 3) v += bias[n];
            if (EPI == 1) {
                v += Ex[(long)m*N + n];
                if (m == n) v = -1e9f;
                v *= TEMP_INV;
            }
            if (EPI == 2) v += Ex[(long)m*N + n];
            if (EPI == 3) v = 0.5f*v*(1.0f + erff(v*0.7071067811865475f));
            C[(long)m*N + n] = v;
        }
    }
}

// ---------------- top-32 + log-softmax weights ----------------
__global__ __launch_bounds__(256) void topk_kernel(
    const float* __restrict__ scores, int* __restrict__ routes,
    float* __restrict__ logw)
{
    int row = blockIdx.x;                 // b*576 + p
    const float* srw = scores + (long)row*PP;
    __shared__ float sv[PP];
    __shared__ float rv[256];
    __shared__ int   ri[256];
    __shared__ float tops[KWIN];
    __shared__ float lse_s;
    int tid = threadIdx.x;
    for (int i = tid; i < PP; i += 256) sv[i] = srw[i];
    __syncthreads();

    for (int t = 0; t < KWIN; t++) {
        float bv = -INFINITY; int bi = -1;
        for (int i = tid; i < PP; i += 256) {
            float v = sv[i];
            if (v > bv) { bv = v; bi = i; }
        }
        rv[tid] = bv; ri[tid] = bi;
        __syncthreads();
        for (int o = 128; o > 0; o >>= 1) {
            if (tid < o) {
                float v2 = rv[tid+o]; int i2 = ri[tid+o];
                if (v2 > rv[tid] || (v2 == rv[tid] && i2 < ri[tid])) { rv[tid] = v2; ri[tid] = i2; }
            }
            __syncthreads();
        }
        if (tid == 0) {
            tops[t] = rv[0];
            routes[(long)row*KWIN + t] = ri[0];
            sv[ri[0]] = -INFINITY;
        }
        __syncthreads();
    }
    if (tid == 0) {
        float m = tops[0], z = 0.f;
        for (int i = 0; i < KWIN; i++) z += expf(tops[i]-m);
        lse_s = m + logf(z);
    }
    __syncthreads();
    if (tid < KWIN)
        logw[(long)row*KWIN + tid] = fmaxf(tops[tid]-lse_s, -10.0f);
}

// ---------------- CLS attention (full softmax over 577 keys) ----------------
__global__ __launch_bounds__(256) void cls_attn_kernel(
    const float* __restrict__ qkv, float* __restrict__ attn)
{
    int b = blockIdx.x / HH, h = blockIdx.x % HH;
    const float* base = qkv + (long)b*SS*3*DD;
    int tid = threadIdx.x;
    __shared__ float qv[HDIM];
    __shared__ float sc[SS];
    __shared__ float red[256];
    __shared__ float m_s, z_s;
    if (tid < HDIM) qv[tid] = base[h*HDIM + tid];       // s=0, Q section
    __syncthreads();

    float lmax = -INFINITY;
    for (int k = tid; k < SS; k += 256) {
        const float* kr = base + (long)k*3*DD + DD + h*HDIM;
        float dot = 0.f;
        #pragma unroll
        for (int d = 0; d < HDIM; d++) dot = fmaf(qv[d], kr[d], dot);
        float s = dot * SCALE_ATT;
        sc[k] = s;
        lmax = fmaxf(lmax, s);
    }
    red[tid] = lmax;
    __syncthreads();
    for (int o = 128; o > 0; o >>= 1) {
        if (tid < o) red[tid] = fmaxf(red[tid], red[tid+o]);
        __syncthreads();
    }
    if (tid == 0) m_s = red[0];
    __syncthreads();
    float m = m_s, lsum = 0.f;
    for (int k = tid; k < SS; k += 256) {
        float e = expf(sc[k]-m); sc[k] = e; lsum += e;
    }
    red[tid] = lsum;
    __syncthreads();
    for (int o = 128; o > 0; o >>= 1) {
        if (tid < o) red[tid] += red[tid+o];
        __syncthreads();
    }
    if (tid == 0) z_s = red[0];
    __syncthreads();
    float zinv = 1.0f / z_s;

    int d = tid & 63, part = tid >> 6;   // 4 partial accumulators per dim
    float acc = 0.f;
    for (int k = part; k < SS; k += 4)
        acc = fmaf(sc[k], base[(long)k*3*DD + 2*DD + h*HDIM + d], acc);
    __shared__ float ro[4][HDIM];
    ro[part][d] = acc;
    __syncthreads();
    if (tid < HDIM)
        attn[((long)b*SS)*DD + h*HDIM + tid] =
            (ro[0][tid]+ro[1][tid]+ro[2][tid]+ro[3][tid]) * zinv;
}

// ---------------- Patch attention over gathered 32-key windows ----------------
__global__ __launch_bounds__(64) void patch_attn_kernel(
    const float* __restrict__ qkv, const int* __restrict__ routes,
    const float* __restrict__ logw, float* __restrict__ attn)
{
    int id = blockIdx.x;
    int p = id % PP;
    int h = (id / PP) % HH;
    int b = id / (PP*HH);
    const float* base = qkv + (long)b*SS*3*DD;
    int tid = threadIdx.x;

    __shared__ float qs[HDIM];
    __shared__ int   sr[KWIN];
    __shared__ float sa[KWIN];
    __shared__ float part[2][KWIN];

    qs[tid] = base[(long)(p+1)*3*DD + h*HDIM + tid];
    if (tid < KWIN) sr[tid] = routes[((long)b*PP + p)*KWIN + tid];
    __syncthreads();

    int k = tid & 31, half = tid >> 5;
    const float* kr = base + (long)(sr[k]+1)*3*DD + DD + h*HDIM + half*32;
    float dot = 0.f;
    #pragma unroll
    for (int d = 0; d < 32; d++) dot = fmaf(qs[half*32+d], kr[d], dot);
    part[half][k] = dot;
    __syncthreads();

    if (tid < KWIN) {
        float s = (part[0][k]+part[1][k]) * SCALE_ATT
                + logw[((long)b*PP + p)*KWIN + k];
        float m = s;
        #pragma unroll
        for (int o = 16; o > 0; o >>= 1) m = fmaxf(m, __shfl_xor_sync(0xffffffffu, m, o));
        float e = expf(s-m);
        float z = e;
        #pragma unroll
        for (int o = 16; o > 0; o >>= 1) z += __shfl_xor_sync(0xffffffffu, z, o);
        sa[k] = e / z;
    }
    __syncthreads();

    float acc = 0.f;
    #pragma unroll 8
    for (int kk = 0; kk < KWIN; kk++)
        acc = fmaf(sa[kk], base[(long)(sr[kk]+1)*3*DD + 2*DD + h*HDIM + tid], acc);
    attn[((long)b*SS + p+1)*DD + h*HDIM + tid] = acc;
}

// ---------------- launcher ----------------
extern "C" void kernel_launch(void* const* d_in, const int* in_sizes, int n_in,
                              void* d_out, int out_size)
{
    const float* x      = (const float*)d_in[0];
    const float* g1     = (const float*)d_in[1];
    const float* b1     = (const float*)d_in[2];
    const float* wq     = (const float*)d_in[3];
    const float* bq     = (const float*)d_in[4];
    const float* wk     = (const float*)d_in[5];
    const float* bk     = (const float*)d_in[6];
    const float* posb   = (const float*)d_in[7];
    const float* w_qkv  = (const float*)d_in[8];
    const float* b_qkv  = (const float*)d_in[9];
    const float* w_proj = (const float*)d_in[10];
    const float* b_proj = (const float*)d_in[11];
    const float* g2     = (const float*)d_in[12];
    const float* b2     = (const float*)d_in[13];
    const float* w_mlp1 = (const float*)d_in[14];
    const float* b_mlp1 = (const float*)d_in[15];
    const float* w_mlp2 = (const float*)d_in[16];
    const float* b_mlp2 = (const float*)d_in[17];
    float* out = (float*)d_out;

    float *xn, *q, *k, *scores, *logw, *qkvb, *attn, *x1, *xn2, *hbuf;
    int *routes;
    cudaGetSymbolAddress((void**)&xn,     g_xn);
    cudaGetSymbolAddress((void**)&q,      g_q);
    cudaGetSymbolAddress((void**)&k,      g_k);
    cudaGetSymbolAddress((void**)&scores, g_scores);
    cudaGetSymbolAddress((void**)&routes, g_routes);
    cudaGetSymbolAddress((void**)&logw,   g_logw);
    cudaGetSymbolAddress((void**)&qkvb,   g_qkv);
    cudaGetSymbolAddress((void**)&attn,   g_attn);
    cudaGetSymbolAddress((void**)&x1,     g_x1);
    cudaGetSymbolAddress((void**)&xn2,    g_xn2);
    cudaGetSymbolAddress((void**)&hbuf,   g_h);

    // 1. LN1
    ln_kernel<<<NROWS, 256>>>(x, g1, b1, xn);

    // 2/3. q,k routing projections on xn[:,1:,:]  (batched, skip CLS row)
    {
        dim3 grid((DD+127)/128, (PP+127)/128, BB);
        sgemm_kernel<0,0><<<grid, 256>>>(xn + DD, wq, q, PP, DD, DD,
                                         (long)SS*DD, 0, (long)PP*DD,
                                         bq, nullptr, 0);
        sgemm_kernel<0,0><<<grid, 256>>>(xn + DD, wk, k, PP, DD, DD,
                                         (long)SS*DD, 0, (long)PP*DD,
                                         bk, nullptr, 0);
    }
    // 4. l2 normalize
    l2norm_kernel<<<BB*PP, 256>>>(q);
    l2norm_kernel<<<BB*PP, 256>>>(k);

    // 5. routing scores = q @ k^T (+pos_bias, diag mask, /TEMP)
    {
        dim3 grid((PP+127)/128, (PP+127)/128, BB);
        sgemm_kernel<1,1><<<grid, 256>>>(q, k, scores, PP, PP, DD,
                                         (long)PP*DD, (long)PP*DD, (long)PP*PP,
                                         nullptr, posb, 0);
    }
    // 6. top-32 + log-softmax weights
    topk_kernel<<<BB*PP, 256>>>(scores, routes, logw);

    // 7. QKV projection
    {
        dim3 grid((3*DD+127)/128, (NROWS+127)/128, 1);
        sgemm_kernel<0,0><<<grid, 256>>>(xn, w_qkv, qkvb, NROWS, 3*DD, DD,
                                         0, 0, 0, b_qkv, nullptr, 0);
    }
    // 8. CLS attention
    cls_attn_kernel<<<BB*HH, 256>>>(qkvb, attn);
    // 9. patch attention
    patch_attn_kernel<<<BB*HH*PP, 64>>>(qkvb, routes, logw, attn);

    // 10. proj + residual x
    {
        dim3 grid((DD+127)/128, (NROWS+127)/128, 1);
        sgemm_kernel<2,0><<<grid, 256>>>(attn, w_proj, x1, NROWS, DD, DD,
                                         0, 0, 0, b_proj, x, 0);
    }
    // 11. LN2
    ln_kernel<<<NROWS, 256>>>(x1, g2, b2, xn2);

    // 12. MLP1 + exact GELU
    {
        dim3 grid((MLPD+127)/128, (NROWS+127)/128, 1);
        sgemm_kernel<3,0><<<grid, 256>>>(xn2, w_mlp1, hbuf, NROWS, MLPD, DD,
                                         0, 0, 0, b_mlp1, nullptr, 0);
    }
    // 13. MLP2 + residual x1 -> out
    {
        dim3 grid((DD+127)/128, (NROWS+127)/128, 1);
        sgemm_kernel<2,0><<<grid, 256>>>(hbuf, w_mlp2, out, NROWS, DD, MLPD,
                                         0, 0, 0, b_mlp2, x1, 0);
    }
}

// round 2
// speedup vs baseline: 1.7055x; 1.7055x over previous
#include <cuda_runtime.h>
#include <math.h>
#include <stdint.h>

// ---------------- problem constants ----------------
#define BB   8
#define SS   577
#define DD   768
#define HH   12
#define HDIM 64
#define PP   576
#define KWIN 32
#define MLPD 3072
#define NROWS (BB*SS)        // 4616
#define SCALE_ATT 0.125f     // 64^-0.5
#define TEMP_INV  10.0f

// ---------------- scratch (device globals, no allocation) ----------------
__device__ float g_xn   [(size_t)BB*SS*DD];
__device__ float g_q    [(size_t)BB*PP*DD];
__device__ float g_k    [(size_t)BB*PP*DD];
__device__ float g_scores[(size_t)BB*PP*PP];
__device__ int   g_routes[(size_t)BB*PP*KWIN];
__device__ float g_logw  [(size_t)BB*PP*KWIN];
__device__ float g_qkv  [(size_t)BB*SS*3*DD];
__device__ float g_attn [(size_t)BB*SS*DD];
__device__ float g_x1   [(size_t)BB*SS*DD];
__device__ float g_xn2  [(size_t)BB*SS*DD];
__device__ float g_h    [(size_t)BB*SS*MLPD];

// ---------------- LayerNorm ----------------
__global__ __launch_bounds__(256) void ln_kernel(
    const float* __restrict__ x, const float* __restrict__ g,
    const float* __restrict__ b, float* __restrict__ y)
{
    int row = blockIdx.x;
    const float* xr = x + (long)row*DD;
    float s = 0.f, sq = 0.f;
    for (int d = threadIdx.x; d < DD; d += 256) {
        float v = xr[d]; s += v; sq += v*v;
    }
    __shared__ float rs[256], rq[256];
    rs[threadIdx.x] = s; rq[threadIdx.x] = sq;
    __syncthreads();
    for (int o = 128; o > 0; o >>= 1) {
        if (threadIdx.x < o) { rs[threadIdx.x] += rs[threadIdx.x+o]; rq[threadIdx.x] += rq[threadIdx.x+o]; }
        __syncthreads();
    }
    __shared__ float mean_s, rstd_s;
    if (threadIdx.x == 0) {
        float mean = rs[0] / (float)DD;
        float var  = rq[0] / (float)DD - mean*mean;
        mean_s = mean;
        rstd_s = rsqrtf(var + 1e-5f);
    }
    __syncthreads();
    float mean = mean_s, rstd = rstd_s;
    float* yr = y + (long)row*DD;
    for (int d = threadIdx.x; d < DD; d += 256)
        yr[d] = (xr[d]-mean)*rstd*g[d] + b[d];
}

// ---------------- L2 normalize rows (in place) ----------------
__global__ __launch_bounds__(256) void l2norm_kernel(float* __restrict__ x)
{
    int row = blockIdx.x;
    float* xr = x + (long)row*DD;
    float sq = 0.f;
    for (int d = threadIdx.x; d < DD; d += 256) { float v = xr[d]; sq += v*v; }
    __shared__ float rq[256];
    rq[threadIdx.x] = sq;
    __syncthreads();
    for (int o = 128; o > 0; o >>= 1) {
        if (threadIdx.x < o) rq[threadIdx.x] += rq[threadIdx.x+o];
        __syncthreads();
    }
    __shared__ float inv_s;
    if (threadIdx.x == 0) {
        float nrm = sqrtf(rq[0]);
        inv_s = 1.0f / fmaxf(nrm, 1e-12f);
    }
    __syncthreads();
    float inv = inv_s;
    for (int d = threadIdx.x; d < DD; d += 256) xr[d] *= inv;
}

// ---------------- fp32 SGEMM (routing path only) ----------------
// EPI: 0 = +bias ; 1 = scores (+pos_bias, diag mask, *1/TEMP)
template<int EPI, int TRANSB>
__global__ __launch_bounds__(256) void sgemm_kernel(
    const float* __restrict__ A, const float* __restrict__ Bm,
    float* __restrict__ C, int M, int N, int K,
    long sA, long sB, long sC,
    const float* __restrict__ bias,
    const float* __restrict__ extra, long sE)
{
    const int BM = 128, BN = 128, BK = 16;
    __shared__ float As[BK][BM+4];
    __shared__ float Bs[BK][BN+4];

    int bz = blockIdx.z;
    A  += bz*sA;
    Bm += bz*sB;
    C  += bz*sC;
    const float* Ex = extra ? (extra + bz*sE) : nullptr;

    int bm = blockIdx.y * BM;
    int bn = blockIdx.x * BN;
    int tid = threadIdx.x;
    int tx = tid & 15, ty = tid >> 4;

    float acc[8][8];
    #pragma unroll
    for (int i = 0; i < 8; i++)
        #pragma unroll
        for (int j = 0; j < 8; j++) acc[i][j] = 0.f;

    int a_r = tid >> 2;
    int a_c = (tid & 3) * 4;
    int b_r = tid >> 5;
    int b_c = (tid & 31) * 4;

    for (int k0 = 0; k0 < K; k0 += BK) {
        #pragma unroll
        for (int pp = 0; pp < 2; pp++) {
            int m = bm + a_r + pp*64;
            float4 v = make_float4(0.f,0.f,0.f,0.f);
            if (m < M) v = *reinterpret_cast<const float4*>(A + (long)m*K + k0 + a_c);
            As[a_c+0][a_r+pp*64] = v.x;
            As[a_c+1][a_r+pp*64] = v.y;
            As[a_c+2][a_r+pp*64] = v.z;
            As[a_c+3][a_r+pp*64] = v.w;
        }
        if (TRANSB) {
            #pragma unroll
            for (int pp = 0; pp < 2; pp++) {
                int n = bn + a_r + pp*64;
                float4 v = make_float4(0.f,0.f,0.f,0.f);
                if (n < N) v = *reinterpret_cast<const float4*>(Bm + (long)n*K + k0 + a_c);
                Bs[a_c+0][a_r+pp*64] = v.x;
                Bs[a_c+1][a_r+pp*64] = v.y;
                Bs[a_c+2][a_r+pp*64] = v.z;
                Bs[a_c+3][a_r+pp*64] = v.w;
            }
        } else {
            #pragma unroll
            for (int pp = 0; pp < 2; pp++) {
                int kk = k0 + b_r + pp*8;
                int n  = bn + b_c;
                float4 v = make_float4(0.f,0.f,0.f,0.f);
                if (n < N) v = *reinterpret_cast<const float4*>(Bm + (long)kk*N + n);
                *reinterpret_cast<float4*>(&Bs[b_r+pp*8][b_c]) = v;
            }
        }
        __syncthreads();

        #pragma unroll
        for (int kk = 0; kk < BK; kk++) {
            float a[8], bfrag[8];
            #pragma unroll
            for (int i = 0; i < 4; i++) {
                a[i]       = As[kk][ty*4+i];
                a[i+4]     = As[kk][64+ty*4+i];
                bfrag[i]   = Bs[kk][tx*4+i];
                bfrag[i+4] = Bs[kk][64+tx*4+i];
            }
            #pragma unroll
            for (int i = 0; i < 8; i++)
                #pragma unroll
                for (int j = 0; j < 8; j++)
                    acc[i][j] = fmaf(a[i], bfrag[j], acc[i][j]);
        }
        __syncthreads();
    }

    #pragma unroll
    for (int i = 0; i < 8; i++) {
        int m = bm + ((i < 4) ? (ty*4+i) : (64+ty*4+(i-4)));
        if (m >= M) continue;
        #pragma unroll
        for (int j = 0; j < 8; j++) {
            int n = bn + ((j < 4) ? (tx*4+j) : (64+tx*4+(j-4)));
            if (n >= N) continue;
            float v = acc[i][j];
            if (EPI == 0) v += bias[n];
            if (EPI == 1) {
                v += Ex[(long)m*N + n];
                if (m == n) v = -1e9f;
                v *= TEMP_INV;
            }
            C[(long)m*N + n] = v;
        }
    }
}

// ---------------- TF32 tensor-core GEMM ----------------
// EPI: 0 = +bias ; 2 = +bias +residual ; 3 = +bias, exact GELU
// C[M,N] = A[M,K] @ B[K,N]. N % 128 == 0, K % 16 == 0. M edge predicated.
__device__ __forceinline__ uint32_t f2tf32(float x) {
    uint32_t r;
    asm volatile("cvt.rna.tf32.f32 %0, %1;" : "=r"(r) : "f"(x));
    return r;
}
__device__ __forceinline__ void cp16(void* dst_smem, const void* src, int srcsize) {
    uint32_t d = (uint32_t)__cvta_generic_to_shared(dst_smem);
    asm volatile("cp.async.cg.shared.global [%0], [%1], 16, %2;"
                 :: "r"(d), "l"(src), "r"(srcsize));
}
__device__ __forceinline__ void mma_tf32(float* d, const uint32_t* a, const uint32_t* b) {
    asm volatile(
        "mma.sync.aligned.m16n8k8.row.col.f32.tf32.tf32.f32 "
        "{%0,%1,%2,%3}, {%4,%5,%6,%7}, {%8,%9}, {%0,%1,%2,%3};"
        : "+f"(d[0]), "+f"(d[1]), "+f"(d[2]), "+f"(d[3])
        : "r"(a[0]), "r"(a[1]), "r"(a[2]), "r"(a[3]), "r"(b[0]), "r"(b[1]));
}

#define TBM 128
#define TBN 128
#define TBK 16
#define ASTRIDE 20    // 16 + 4  -> bank = (20r + c) % 32 conflict-free
#define BSTRIDE 136   // 128 + 8 -> bank = (8t + c) % 32 conflict-free

template<int EPI>
__global__ __launch_bounds__(256) void tf32_gemm_kernel(
    const float* __restrict__ A, const float* __restrict__ B,
    float* __restrict__ C, int M, int N, int K,
    const float* __restrict__ bias, const float* __restrict__ resid)
{
    __shared__ float As[2][TBM][ASTRIDE];
    __shared__ float Bs[2][TBK][BSTRIDE];

    int tid  = threadIdx.x;
    int wid  = tid >> 5, lane = tid & 31;
    int wr   = wid & 1;          // warp row: 2 x 64
    int wc   = wid >> 1;         // warp col: 4 x 32
    int bm   = blockIdx.y * TBM;
    int bn   = blockIdx.x * TBN;
    int g    = lane >> 2;        // group 0..7
    int t    = lane & 3;

    float acc[4][4][4];
    #pragma unroll
    for (int i = 0; i < 4; i++)
        #pragma unroll
        for (int j = 0; j < 4; j++)
            #pragma unroll
            for (int r = 0; r < 4; r++) acc[i][j][r] = 0.f;

    int a_row = tid >> 2;          // 0..63 (two passes -> 128)
    int a_col = (tid & 3) * 4;     // 0,4,8,12
    int b_row = tid >> 5;          // 0..7 (two passes -> 16)
    int b_col = (tid & 31) * 4;

    auto load_stage = [&](int buf, int k0) {
        #pragma unroll
        for (int pp = 0; pp < 2; pp++) {
            int gr = bm + a_row + pp*64;
            const float* src = A + (long)gr*K + k0 + a_col;
            cp16(&As[buf][a_row + pp*64][a_col], src, gr < M ? 16 : 0);
        }
        #pragma unroll
        for (int pp = 0; pp < 2; pp++) {
            const float* src = B + (long)(k0 + b_row + pp*8)*N + bn + b_col;
            cp16(&Bs[buf][b_row + pp*8][b_col], src, 16);
        }
        asm volatile("cp.async.commit_group;");
    };

    load_stage(0, 0);
    int buf = 0;
    for (int k0 = 0; k0 < K; k0 += TBK) {
        if (k0 + TBK < K) {
            load_stage(buf ^ 1, k0 + TBK);
            asm volatile("cp.async.wait_group 1;");
        } else {
            asm volatile("cp.async.wait_group 0;");
        }
        __syncthreads();

        #pragma unroll
        for (int ka = 0; ka < 2; ka++) {
            int kk = ka*8;
            uint32_t afrag[4][4];
            #pragma unroll
            for (int ma = 0; ma < 4; ma++) {
                int r = wr*64 + ma*16 + g;
                afrag[ma][0] = f2tf32(As[buf][r  ][kk + t    ]);
                afrag[ma][1] = f2tf32(As[buf][r+8][kk + t    ]);
                afrag[ma][2] = f2tf32(As[buf][r  ][kk + t + 4]);
                afrag[ma][3] = f2tf32(As[buf][r+8][kk + t + 4]);
            }
            uint32_t bfrag[4][2];
            #pragma unroll
            for (int na = 0; na < 4; na++) {
                int c = wc*32 + na*8 + g;
                bfrag[na][0] = f2tf32(Bs[buf][kk + t    ][c]);
                bfrag[na][1] = f2tf32(Bs[buf][kk + t + 4][c]);
            }
            #pragma unroll
            for (int ma = 0; ma < 4; ma++)
                #pragma unroll
                for (int na = 0; na < 4; na++)
                    mma_tf32(acc[ma][na], afrag[ma], bfrag[na]);
        }
        __syncthreads();
        buf ^= 1;
    }

    // epilogue: each (ma,na) tile -> rows g / g+8, cols 2t..2t+1 (float2)
    #pragma unroll
    for (int ma = 0; ma < 4; ma++) {
        int row0 = bm + wr*64 + ma*16 + g;
        #pragma unroll
        for (int na = 0; na < 4; na++) {
            int col = bn + wc*32 + na*8 + 2*t;
            float b0 = bias[col], b1 = bias[col+1];
            #pragma unroll
            for (int half = 0; half < 2; half++) {
                int row = row0 + half*8;
                if (row >= M) continue;
                float v0 = acc[ma][na][half*2+0] + b0;
                float v1 = acc[ma][na][half*2+1] + b1;
                if (EPI == 2) {
                    v0 += resid[(long)row*N + col];
                    v1 += resid[(long)row*N + col + 1];
                }
                if (EPI == 3) {
                    v0 = 0.5f*v0*(1.0f + erff(v0*0.7071067811865475f));
                    v1 = 0.5f*v1*(1.0f + erff(v1*0.7071067811865475f));
                }
                *reinterpret_cast<float2*>(C + (long)row*N + col) = make_float2(v0, v1);
            }
        }
    }
}

// ---------------- top-32 + log-softmax weights ----------------
__global__ __launch_bounds__(256) void topk_kernel(
    const float* __restrict__ scores, int* __restrict__ routes,
    float* __restrict__ logw)
{
    int row = blockIdx.x;                 // b*576 + p
    const float* srw = scores + (long)row*PP;
    __shared__ float sv[PP];
    __shared__ float rv[256];
    __shared__ int   ri[256];
    __shared__ float tops[KWIN];
    __shared__ float lse_s;
    int tid = threadIdx.x;
    for (int i = tid; i < PP; i += 256) sv[i] = srw[i];
    __syncthreads();

    for (int t = 0; t < KWIN; t++) {
        float bv = -INFINITY; int bi = -1;
        for (int i = tid; i < PP; i += 256) {
            float v = sv[i];
            if (v > bv) { bv = v; bi = i; }
        }
        rv[tid] = bv; ri[tid] = bi;
        __syncthreads();
        for (int o = 128; o > 0; o >>= 1) {
            if (tid < o) {
                float v2 = rv[tid+o]; int i2 = ri[tid+o];
                if (v2 > rv[tid] || (v2 == rv[tid] && i2 < ri[tid])) { rv[tid] = v2; ri[tid] = i2; }
            }
            __syncthreads();
        }
        if (tid == 0) {
            tops[t] = rv[0];
            routes[(long)row*KWIN + t] = ri[0];
            sv[ri[0]] = -INFINITY;
        }
        __syncthreads();
    }
    if (tid == 0) {
        float m = tops[0], z = 0.f;
        for (int i = 0; i < KWIN; i++) z += expf(tops[i]-m);
        lse_s = m + logf(z);
    }
    __syncthreads();
    if (tid < KWIN)
        logw[(long)row*KWIN + tid] = fmaxf(tops[tid]-lse_s, -10.0f);
}

// ---------------- CLS attention (full softmax over 577 keys) ----------------
__global__ __launch_bounds__(256) void cls_attn_kernel(
    const float* __restrict__ qkv, float* __restrict__ attn)
{
    int b = blockIdx.x / HH, h = blockIdx.x % HH;
    const float* base = qkv + (long)b*SS*3*DD;
    int tid = threadIdx.x;
    __shared__ float qv[HDIM];
    __shared__ float sc[SS];
    __shared__ float red[256];
    __shared__ float m_s, z_s;
    if (tid < HDIM) qv[tid] = base[h*HDIM + tid];
    __syncthreads();

    float lmax = -INFINITY;
    for (int k = tid; k < SS; k += 256) {
        const float* kr = base + (long)k*3*DD + DD + h*HDIM;
        float dot = 0.f;
        #pragma unroll
        for (int d = 0; d < HDIM; d++) dot = fmaf(qv[d], kr[d], dot);
        float s = dot * SCALE_ATT;
        sc[k] = s;
        lmax = fmaxf(lmax, s);
    }
    red[tid] = lmax;
    __syncthreads();
    for (int o = 128; o > 0; o >>= 1) {
        if (tid < o) red[tid] = fmaxf(red[tid], red[tid+o]);
        __syncthreads();
    }
    if (tid == 0) m_s = red[0];
    __syncthreads();
    float m = m_s, lsum = 0.f;
    for (int k = tid; k < SS; k += 256) {
        float e = expf(sc[k]-m); sc[k] = e; lsum += e;
    }
    red[tid] = lsum;
    __syncthreads();
    for (int o = 128; o > 0; o >>= 1) {
        if (tid < o) red[tid] += red[tid+o];
        __syncthreads();
    }
    if (tid == 0) z_s = red[0];
    __syncthreads();
    float zinv = 1.0f / z_s;

    int d = tid & 63, part = tid >> 6;
    float acc = 0.f;
    for (int k = part; k < SS; k += 4)
        acc = fmaf(sc[k], base[(long)k*3*DD + 2*DD + h*HDIM + d], acc);
    __shared__ float ro[4][HDIM];
    ro[part][d] = acc;
    __syncthreads();
    if (tid < HDIM)
        attn[((long)b*SS)*DD + h*HDIM + tid] =
            (ro[0][tid]+ro[1][tid]+ro[2][tid]+ro[3][tid]) * zinv;
}

// ---------------- Patch attention over gathered 32-key windows ----------------
__global__ __launch_bounds__(64) void patch_attn_kernel(
    const float* __restrict__ qkv, const int* __restrict__ routes,
    const float* __restrict__ logw, float* __restrict__ attn)
{
    int id = blockIdx.x;
    int p = id % PP;
    int h = (id / PP) % HH;
    int b = id / (PP*HH);
    const float* base = qkv + (long)b*SS*3*DD;
    int tid = threadIdx.x;

    __shared__ float qs[HDIM];
    __shared__ int   sr[KWIN];
    __shared__ float sa[KWIN];
    __shared__ float part[2][KWIN];

    qs[tid] = base[(long)(p+1)*3*DD + h*HDIM + tid];
    if (tid < KWIN) sr[tid] = routes[((long)b*PP + p)*KWIN + tid];
    __syncthreads();

    int k = tid & 31, half = tid >> 5;
    const float* kr = base + (long)(sr[k]+1)*3*DD + DD + h*HDIM + half*32;
    float dot = 0.f;
    #pragma unroll
    for (int d = 0; d < 32; d++) dot = fmaf(qs[half*32+d], kr[d], dot);
    part[half][k] = dot;
    __syncthreads();

    if (tid < KWIN) {
        float s = (part[0][k]+part[1][k]) * SCALE_ATT
                + logw[((long)b*PP + p)*KWIN + k];
        float m = s;
        #pragma unroll
        for (int o = 16; o > 0; o >>= 1) m = fmaxf(m, __shfl_xor_sync(0xffffffffu, m, o));
        float e = expf(s-m);
        float z = e;
        #pragma unroll
        for (int o = 16; o > 0; o >>= 1) z += __shfl_xor_sync(0xffffffffu, z, o);
        sa[k] = e / z;
    }
    __syncthreads();

    float acc = 0.f;
    #pragma unroll 8
    for (int kk = 0; kk < KWIN; kk++)
        acc = fmaf(sa[kk], base[(long)(sr[kk]+1)*3*DD + 2*DD + h*HDIM + tid], acc);
    attn[((long)b*SS + p+1)*DD + h*HDIM + tid] = acc;
}

// ---------------- launcher ----------------
extern "C" void kernel_launch(void* const* d_in, const int* in_sizes, int n_in,
                              void* d_out, int out_size)
{
    const float* x      = (const float*)d_in[0];
    const float* g1     = (const float*)d_in[1];
    const float* b1     = (const float*)d_in[2];
    const float* wq     = (const float*)d_in[3];
    const float* bq     = (const float*)d_in[4];
    const float* wk     = (const float*)d_in[5];
    const float* bk     = (const float*)d_in[6];
    const float* posb   = (const float*)d_in[7];
    const float* w_qkv  = (const float*)d_in[8];
    const float* b_qkv  = (const float*)d_in[9];
    const float* w_proj = (const float*)d_in[10];
    const float* b_proj = (const float*)d_in[11];
    const float* g2     = (const float*)d_in[12];
    const float* b2     = (const float*)d_in[13];
    const float* w_mlp1 = (const float*)d_in[14];
    const float* b_mlp1 = (const float*)d_in[15];
    const float* w_mlp2 = (const float*)d_in[16];
    const float* b_mlp2 = (const float*)d_in[17];
    float* out = (float*)d_out;

    float *xn, *q, *k, *scores, *logw, *qkvb, *attn, *x1, *xn2, *hbuf;
    int *routes;
    cudaGetSymbolAddress((void**)&xn,     g_xn);
    cudaGetSymbolAddress((void**)&q,      g_q);
    cudaGetSymbolAddress((void**)&k,      g_k);
    cudaGetSymbolAddress((void**)&scores, g_scores);
    cudaGetSymbolAddress((void**)&routes, g_routes);
    cudaGetSymbolAddress((void**)&logw,   g_logw);
    cudaGetSymbolAddress((void**)&qkvb,   g_qkv);
    cudaGetSymbolAddress((void**)&attn,   g_attn);
    cudaGetSymbolAddress((void**)&x1,     g_x1);
    cudaGetSymbolAddress((void**)&xn2,    g_xn2);
    cudaGetSymbolAddress((void**)&hbuf,   g_h);

    // 1. LN1
    ln_kernel<<<NROWS, 256>>>(x, g1, b1, xn);

    // 2/3. q,k routing projections on xn[:,1:,:]  (fp32 — protects top-k)
    {
        dim3 grid((DD+127)/128, (PP+127)/128, BB);
        sgemm_kernel<0,0><<<grid, 256>>>(xn + DD, wq, q, PP, DD, DD,
                                         (long)SS*DD, 0, (long)PP*DD,
                                         bq, nullptr, 0);
        sgemm_kernel<0,0><<<grid, 256>>>(xn + DD, wk, k, PP, DD, DD,
                                         (long)SS*DD, 0, (long)PP*DD,
                                         bk, nullptr, 0);
    }
    // 4. l2 normalize
    l2norm_kernel<<<BB*PP, 256>>>(q);
    l2norm_kernel<<<BB*PP, 256>>>(k);

    // 5. routing scores = q @ k^T (+pos_bias, diag mask, /TEMP)  (fp32)
    {
        dim3 grid((PP+127)/128, (PP+127)/128, BB);
        sgemm_kernel<1,1><<<grid, 256>>>(q, k, scores, PP, PP, DD,
                                         (long)PP*DD, (long)PP*DD, (long)PP*PP,
                                         nullptr, posb, 0);
    }
    // 6. top-32 + log-softmax weights
    topk_kernel<<<BB*PP, 256>>>(scores, routes, logw);

    // 7. QKV projection (TF32 tensor cores)
    {
        dim3 grid((3*DD)/TBN, (NROWS+TBM-1)/TBM);
        tf32_gemm_kernel<0><<<grid, 256>>>(xn, w_qkv, qkvb, NROWS, 3*DD, DD,
                                           b_qkv, nullptr);
    }
    // 8. CLS attention
    cls_attn_kernel<<<BB*HH, 256>>>(qkvb, attn);
    // 9. patch attention
    patch_attn_kernel<<<BB*HH*PP, 64>>>(qkvb, routes, logw, attn);

    // 10. proj + residual x (TF32)
    {
        dim3 grid(DD/TBN, (NROWS+TBM-1)/TBM);
        tf32_gemm_kernel<2><<<grid, 256>>>(attn, w_proj, x1, NROWS, DD, DD,
                                           b_proj, x);
    }
    // 11. LN2
    ln_kernel<<<NROWS, 256>>>(x1, g2, b2, xn2);

    // 12. MLP1 + exact GELU (TF32)
    {
        dim3 grid(MLPD/TBN, (NROWS+TBM-1)/TBM);
        tf32_gemm_kernel<3><<<grid, 256>>>(xn2, w_mlp1, hbuf, NROWS, MLPD, DD,
                                           b_mlp1, nullptr);
    }
    // 13. MLP2 + residual x1 -> out (TF32)
    {
        dim3 grid(DD/TBN, (NROWS+TBM-1)/TBM);
        tf32_gemm_kernel<2><<<grid, 256>>>(hbuf, w_mlp2, out, NROWS, DD, MLPD,
                                           b_mlp2, x1);
    }
}

// round 4
// speedup vs baseline: 1.8545x; 1.0874x over previous
#include <cuda_runtime.h>
#include <math.h>
#include <stdint.h>

// ---------------- problem constants ----------------
#define BB   8
#define SS   577
#define DD   768
#define HH   12
#define HDIM 64
#define PP   576
#define KWIN 32
#define MLPD 3072
#define NROWS (BB*SS)        // 4616
#define SCALE_ATT 0.125f
#define TEMP_INV  10.0f

__device__ __forceinline__ uint32_t f2tf32(float x) {
    uint32_t r;
    asm volatile("cvt.rna.tf32.f32 %0, %1;" : "=r"(r) : "f"(x));
    return r;
}
__device__ __forceinline__ float tf32r(float x) {
    return __uint_as_float(f2tf32(x));
}
__device__ __forceinline__ void cp16(void* dst_smem, const void* src, int srcsize) {
    uint32_t d = (uint32_t)__cvta_generic_to_shared(dst_smem);
    asm volatile("cp.async.cg.shared.global [%0], [%1], 16, %2;"
                 :: "r"(d), "l"(src), "r"(srcsize));
}
__device__ __forceinline__ void mma_tf32(float* d, const uint32_t* a, const uint32_t* b) {
    asm volatile(
        "mma.sync.aligned.m16n8k8.row.col.f32.tf32.tf32.f32 "
        "{%0,%1,%2,%3}, {%4,%5,%6,%7}, {%8,%9}, {%0,%1,%2,%3};"
        : "+f"(d[0]), "+f"(d[1]), "+f"(d[2]), "+f"(d[3])
        : "r"(a[0]), "r"(a[1]), "r"(a[2]), "r"(a[3]), "r"(b[0]), "r"(b[1]));
}

// ---------------- scratch (device globals) ----------------
__device__ float g_xn   [(size_t)BB*SS*DD];      // fp32 LN1 out (routing)
__device__ float g_xnr  [(size_t)BB*SS*DD];      // tf32-rounded LN1 out (QKV gemm)
__device__ float g_q    [(size_t)BB*PP*DD];
__device__ float g_k    [(size_t)BB*PP*DD];
__device__ float g_scores[(size_t)BB*PP*PP];
__device__ int   g_routes[(size_t)BB*PP*KWIN];
__device__ float g_logw  [(size_t)BB*PP*KWIN];
__device__ float g_qkv  [(size_t)BB*SS*3*DD];
__device__ float g_attn [(size_t)BB*SS*DD];
__device__ float g_x1   [(size_t)BB*SS*DD];
__device__ float g_xn2  [(size_t)BB*SS*DD];
__device__ float g_h    [(size_t)BB*SS*MLPD];
// pre-rounded (tf32) weights for tensor-core GEMMs
__device__ float g_rqkv [(size_t)DD*3*DD];
__device__ float g_rproj[(size_t)DD*DD];
__device__ float g_rm1  [(size_t)DD*MLPD];
__device__ float g_rm2  [(size_t)MLPD*DD];

// ---------------- elementwise tf32 rounding ----------------
__global__ __launch_bounds__(256) void round_tf32_kernel(
    const float* __restrict__ src, float* __restrict__ dst, int n)
{
    int i = blockIdx.x*256 + threadIdx.x;
    if (i < n) dst[i] = tf32r(src[i]);
}

// ---------------- LayerNorm (optional second, tf32-rounded output) --------
__global__ __launch_bounds__(256) void ln_kernel(
    const float* __restrict__ x, const float* __restrict__ g,
    const float* __restrict__ b, float* __restrict__ y,
    float* __restrict__ yr)
{
    int row = blockIdx.x;
    const float* xr = x + (long)row*DD;
    float s = 0.f, sq = 0.f;
    for (int d = threadIdx.x; d < DD; d += 256) {
        float v = xr[d]; s += v; sq += v*v;
    }
    __shared__ float rs[256], rq[256];
    rs[threadIdx.x] = s; rq[threadIdx.x] = sq;
    __syncthreads();
    for (int o = 128; o > 0; o >>= 1) {
        if (threadIdx.x < o) { rs[threadIdx.x] += rs[threadIdx.x+o]; rq[threadIdx.x] += rq[threadIdx.x+o]; }
        __syncthreads();
    }
    __shared__ float mean_s, rstd_s;
    if (threadIdx.x == 0) {
        float mean = rs[0] / (float)DD;
        float var  = rq[0] / (float)DD - mean*mean;
        mean_s = mean;
        rstd_s = rsqrtf(var + 1e-5f);
    }
    __syncthreads();
    float mean = mean_s, rstd = rstd_s;
    float* ybase  = y  ? (y  + (long)row*DD) : nullptr;
    float* yrbase = yr ? (yr + (long)row*DD) : nullptr;
    for (int d = threadIdx.x; d < DD; d += 256) {
        float v = (xr[d]-mean)*rstd*g[d] + b[d];
        if (ybase)  ybase[d]  = v;
        if (yrbase) yrbase[d] = tf32r(v);
    }
}

// ---------------- L2 normalize rows (fp32, in place) ----------------
__global__ __launch_bounds__(256) void l2norm_kernel(float* __restrict__ x)
{
    int row = blockIdx.x;
    float* xr = x + (long)row*DD;
    float sq = 0.f;
    for (int d = threadIdx.x; d < DD; d += 256) { float v = xr[d]; sq += v*v; }
    __shared__ float rq[256];
    rq[threadIdx.x] = sq;
    __syncthreads();
    for (int o = 128; o > 0; o >>= 1) {
        if (threadIdx.x < o) rq[threadIdx.x] += rq[threadIdx.x+o];
        __syncthreads();
    }
    __shared__ float inv_s;
    if (threadIdx.x == 0) inv_s = 1.0f / fmaxf(sqrtf(rq[0]), 1e-12f);
    __syncthreads();
    float inv = inv_s;
    for (int d = threadIdx.x; d < DD; d += 256) xr[d] *= inv;
}

// ---------------- fp32 SGEMM (routing path only) ----------------
// EPI: 0 = +bias ; 1 = scores (+pos_bias, diag mask, *1/TEMP)
template<int EPI, int TRANSB>
__global__ __launch_bounds__(256) void sgemm_kernel(
    const float* __restrict__ A, const float* __restrict__ Bm,
    float* __restrict__ C, int M, int N, int K,
    long sA, long sB, long sC,
    const float* __restrict__ bias,
    const float* __restrict__ extra, long sE)
{
    const int BM = 128, BN = 128, BK = 16;
    __shared__ float As[BK][BM+4];
    __shared__ float Bs[BK][BN+4];

    int bz = blockIdx.z;
    A  += bz*sA;
    Bm += bz*sB;
    C  += bz*sC;
    const float* Ex = extra ? (extra + bz*sE) : nullptr;

    int bm = blockIdx.y * BM;
    int bn = blockIdx.x * BN;
    int tid = threadIdx.x;
    int tx = tid & 15, ty = tid >> 4;

    float acc[8][8];
    #pragma unroll
    for (int i = 0; i < 8; i++)
        #pragma unroll
        for (int j = 0; j < 8; j++) acc[i][j] = 0.f;

    int a_r = tid >> 2;
    int a_c = (tid & 3) * 4;
    int b_r = tid >> 5;
    int b_c = (tid & 31) * 4;

    for (int k0 = 0; k0 < K; k0 += BK) {
        #pragma unroll
        for (int pp = 0; pp < 2; pp++) {
            int m = bm + a_r + pp*64;
            float4 v = make_float4(0.f,0.f,0.f,0.f);
            if (m < M) v = *reinterpret_cast<const float4*>(A + (long)m*K + k0 + a_c);
            As[a_c+0][a_r+pp*64] = v.x;
            As[a_c+1][a_r+pp*64] = v.y;
            As[a_c+2][a_r+pp*64] = v.z;
            As[a_c+3][a_r+pp*64] = v.w;
        }
        if (TRANSB) {
            #pragma unroll
            for (int pp = 0; pp < 2; pp++) {
                int n = bn + a_r + pp*64;
                float4 v = make_float4(0.f,0.f,0.f,0.f);
                if (n < N) v = *reinterpret_cast<const float4*>(Bm + (long)n*K + k0 + a_c);
                Bs[a_c+0][a_r+pp*64] = v.x;
                Bs[a_c+1][a_r+pp*64] = v.y;
                Bs[a_c+2][a_r+pp*64] = v.z;
                Bs[a_c+3][a_r+pp*64] = v.w;
            }
        } else {
            #pragma unroll
            for (int pp = 0; pp < 2; pp++) {
                int kk = k0 + b_r + pp*8;
                int n  = bn + b_c;
                float4 v = make_float4(0.f,0.f,0.f,0.f);
                if (n < N) v = *reinterpret_cast<const float4*>(Bm + (long)kk*N + n);
                *reinterpret_cast<float4*>(&Bs[b_r+pp*8][b_c]) = v;
            }
        }
        __syncthreads();

        #pragma unroll
        for (int kk = 0; kk < BK; kk++) {
            float a[8], bfrag[8];
            #pragma unroll
            for (int i = 0; i < 4; i++) {
                a[i]       = As[kk][ty*4+i];
                a[i+4]     = As[kk][64+ty*4+i];
                bfrag[i]   = Bs[kk][tx*4+i];
                bfrag[i+4] = Bs[kk][64+tx*4+i];
            }
            #pragma unroll
            for (int i = 0; i < 8; i++)
                #pragma unroll
                for (int j = 0; j < 8; j++)
                    acc[i][j] = fmaf(a[i], bfrag[j], acc[i][j]);
        }
        __syncthreads();
    }

    #pragma unroll
    for (int i = 0; i < 8; i++) {
        int m = bm + ((i < 4) ? (ty*4+i) : (64+ty*4+(i-4)));
        if (m >= M) continue;
        #pragma unroll
        for (int j = 0; j < 8; j++) {
            int n = bn + ((j < 4) ? (tx*4+j) : (64+tx*4+(j-4)));
            if (n >= N) continue;
            float v = acc[i][j];
            if (EPI == 0) v += bias[n];
            if (EPI == 1) {
                v += Ex[(long)m*N + n];
                if (m == n) v = -1e9f;
                v *= TEMP_INV;
            }
            C[(long)m*N + n] = v;
        }
    }
}

// ---------------- TF32 NN GEMM, 3-stage cp.async, no inner cvt ----------------
// EPI: 0 = +bias ; 2 = +bias +residual ; 3 = +bias + exact GELU (out rounded)
// A,B pre-rounded to tf32. N%128==0, K%16==0. M edge predicated.
#define TBM 128
#define TBN 128
#define TBK 16
#define ASTR 20
#define BSTR 136

template<int EPI>
__global__ __launch_bounds__(256) void tf32_nn_kernel(
    const float* __restrict__ A, const float* __restrict__ B,
    float* __restrict__ C, int M, int N, int K, int lda,
    const float* __restrict__ bias, const float* __restrict__ resid)
{
    __shared__ float As[3][TBM][ASTR];
    __shared__ float Bs[3][TBK][BSTR];

    int tid  = threadIdx.x;
    int wid  = tid >> 5, lane = tid & 31;
    int wr   = wid & 1;
    int wc   = wid >> 1;
    int bm   = blockIdx.y * TBM;
    int bn   = blockIdx.x * TBN;
    int g    = lane >> 2;
    int t    = lane & 3;

    float acc[4][4][4];
    #pragma unroll
    for (int i = 0; i < 4; i++)
        #pragma unroll
        for (int j = 0; j < 4; j++)
            #pragma unroll
            for (int r = 0; r < 4; r++) acc[i][j][r] = 0.f;

    int a_row = tid >> 2;
    int a_col = (tid & 3) * 4;
    int b_row = tid >> 5;
    int b_col = (tid & 31) * 4;

    auto load_stage = [&](int buf, int k0) {
        #pragma unroll
        for (int pp = 0; pp < 2; pp++) {
            int m = bm + a_row + pp*64;
            cp16(&As[buf][a_row + pp*64][a_col],
                 A + (long)m*lda + k0 + a_col, m < M ? 16 : 0);
        }
        #pragma unroll
        for (int pp = 0; pp < 2; pp++)
            cp16(&Bs[buf][b_row + pp*8][b_col],
                 B + (long)(k0 + b_row + pp*8)*N + bn + b_col, 16);
        asm volatile("cp.async.commit_group;");
    };

    int KT = K / TBK;
    load_stage(0, 0);
    load_stage(1, TBK);
    int buf = 0;
    for (int kt = 0; kt < KT; kt++) {
        if (kt == KT-1) asm volatile("cp.async.wait_group 0;");
        else            asm volatile("cp.async.wait_group 1;");
        __syncthreads();
        if (kt + 2 < KT) load_stage((kt+2)%3, (kt+2)*TBK);

        #pragma unroll
        for (int ka = 0; ka < 2; ka++) {
            int kk = ka*8;
            uint32_t afrag[4][4];
            #pragma unroll
            for (int ma = 0; ma < 4; ma++) {
                int r = wr*64 + ma*16 + g;
                afrag[ma][0] = __float_as_uint(As[buf][r  ][kk + t    ]);
                afrag[ma][1] = __float_as_uint(As[buf][r+8][kk + t    ]);
                afrag[ma][2] = __float_as_uint(As[buf][r  ][kk + t + 4]);
                afrag[ma][3] = __float_as_uint(As[buf][r+8][kk + t + 4]);
            }
            uint32_t bfrag[4][2];
            #pragma unroll
            for (int na = 0; na < 4; na++) {
                int c = wc*32 + na*8 + g;
                bfrag[na][0] = __float_as_uint(Bs[buf][kk + t    ][c]);
                bfrag[na][1] = __float_as_uint(Bs[buf][kk + t + 4][c]);
            }
            #pragma unroll
            for (int ma = 0; ma < 4; ma++)
                #pragma unroll
                for (int na = 0; na < 4; na++)
                    mma_tf32(acc[ma][na], afrag[ma], bfrag[na]);
        }
        buf = (buf == 2) ? 0 : buf + 1;
    }

    #pragma unroll
    for (int ma = 0; ma < 4; ma++) {
        int row0 = bm + wr*64 + ma*16 + g;
        #pragma unroll
        for (int na = 0; na < 4; na++) {
            int col = bn + wc*32 + na*8 + 2*t;
            float b0 = bias[col], b1 = bias[col+1];
            #pragma unroll
            for (int half = 0; half < 2; half++) {
                int row = row0 + half*8;
                if (row >= M) continue;
                float v0 = acc[ma][na][half*2+0] + b0;
                float v1 = acc[ma][na][half*2+1] + b1;
                if (EPI == 2) {
                    v0 += resid[(long)row*N + col];
                    v1 += resid[(long)row*N + col + 1];
                }
                if (EPI == 3) {
                    v0 = 0.5f*v0*(1.0f + erff(v0*0.7071067811865475f));
                    v1 = 0.5f*v1*(1.0f + erff(v1*0.7071067811865475f));
                    v0 = tf32r(v0); v1 = tf32r(v1);   // feeds mlp2 MMA
                }
                *reinterpret_cast<float2*>(C + (long)row*N + col) = make_float2(v0, v1);
            }
        }
    }
}

// ---------------- warp-per-row top-32 + log-softmax weights ----------------
__global__ __launch_bounds__(256) void topk_warp_kernel(
    const float* __restrict__ scores, int* __restrict__ routes,
    float* __restrict__ logw)
{
    int warp = blockIdx.x*8 + (threadIdx.x >> 5);
    int lane = threadIdx.x & 31;
    const float* srw = scores + (long)warp*PP;
    float v[18];
    #pragma unroll
    for (int j = 0; j < 18; j++) v[j] = srw[j*32 + lane];

    float myTop = 0.f;
    for (int tt = 0; tt < KWIN; tt++) {
        float bv = -INFINITY; int bj = 0;
        #pragma unroll
        for (int j = 0; j < 18; j++)
            if (v[j] > bv) { bv = v[j]; bj = j; }
        int bi = bj*32 + lane;
        #pragma unroll
        for (int o = 16; o > 0; o >>= 1) {
            float ov = __shfl_xor_sync(0xffffffffu, bv, o);
            int   oi = __shfl_xor_sync(0xffffffffu, bi, o);
            if (ov > bv || (ov == bv && oi < bi)) { bv = ov; bi = oi; }
        }
        if (lane == (bi & 31)) v[bi >> 5] = -INFINITY;
        if (lane == tt) myTop = bv;
        if (lane == 0)  routes[(long)warp*KWIN + tt] = bi;
    }
    float m = __shfl_sync(0xffffffffu, myTop, 0);
    float e = expf(myTop - m);
    float z = e;
    #pragma unroll
    for (int o = 16; o > 0; o >>= 1) z += __shfl_xor_sync(0xffffffffu, z, o);
    float lse = m + logf(z);
    logw[(long)warp*KWIN + lane] = fmaxf(myTop - lse, -10.0f);
}

// ---------------- CLS attention ----------------
__global__ __launch_bounds__(256) void cls_attn_kernel(
    const float* __restrict__ qkv, float* __restrict__ attn)
{
    int b = blockIdx.x / HH, h = blockIdx.x % HH;
    const float* base = qkv + (long)b*SS*3*DD;
    int tid = threadIdx.x;
    __shared__ float qv[HDIM];
    __shared__ float sc[SS];
    __shared__ float red[256];
    __shared__ float m_s, z_s;
    if (tid < HDIM) qv[tid] = base[h*HDIM + tid];
    __syncthreads();

    float lmax = -INFINITY;
    for (int k = tid; k < SS; k += 256) {
        const float* kr = base + (long)k*3*DD + DD + h*HDIM;
        float dot = 0.f;
        #pragma unroll
        for (int d = 0; d < HDIM; d++) dot = fmaf(qv[d], kr[d], dot);
        float s = dot * SCALE_ATT;
        sc[k] = s;
        lmax = fmaxf(lmax, s);
    }
    red[tid] = lmax;
    __syncthreads();
    for (int o = 128; o > 0; o >>= 1) {
        if (tid < o) red[tid] = fmaxf(red[tid], red[tid+o]);
        __syncthreads();
    }
    if (tid == 0) m_s = red[0];
    __syncthreads();
    float m = m_s, lsum = 0.f;
    for (int k = tid; k < SS; k += 256) {
        float e = expf(sc[k]-m); sc[k] = e; lsum += e;
    }
    red[tid] = lsum;
    __syncthreads();
    for (int o = 128; o > 0; o >>= 1) {
        if (tid < o) red[tid] += red[tid+o];
        __syncthreads();
    }
    if (tid == 0) z_s = red[0];
    __syncthreads();
    float zinv = 1.0f / z_s;

    int d = tid & 63, part = tid >> 6;
    float acc = 0.f;
    for (int k = part; k < SS; k += 4)
        acc = fmaf(sc[k], base[(long)k*3*DD + 2*DD + h*HDIM + d], acc);
    __shared__ float ro[4][HDIM];
    ro[part][d] = acc;
    __syncthreads();
    if (tid < HDIM)
        attn[((long)b*SS)*DD + h*HDIM + tid] =
            tf32r((ro[0][tid]+ro[1][tid]+ro[2][tid]+ro[3][tid]) * zinv);
}

// ---------------- Patch attention (gathered 32-key windows) ----------------
__global__ __launch_bounds__(64) void patch_attn_kernel(
    const float* __restrict__ qkv, const int* __restrict__ routes,
    const float* __restrict__ logw, float* __restrict__ attn)
{
    int id = blockIdx.x;
    int p = id % PP;
    int h = (id / PP) % HH;
    int b = id / (PP*HH);
    const float* base = qkv + (long)b*SS*3*DD;
    int tid = threadIdx.x;

    __shared__ float qs[HDIM];
    __shared__ int   sr[KWIN];
    __shared__ float sa[KWIN];
    __shared__ float part[2][KWIN];

    qs[tid] = base[(long)(p+1)*3*DD + h*HDIM + tid];
    if (tid < KWIN) sr[tid] = routes[((long)b*PP + p)*KWIN + tid];
    __syncthreads();

    int k = tid & 31, half = tid >> 5;
    const float* kr = base + (long)(sr[k]+1)*3*DD + DD + h*HDIM + half*32;
    float dot = 0.f;
    #pragma unroll
    for (int d = 0; d < 32; d++) dot = fmaf(qs[half*32+d], kr[d], dot);
    part[half][k] = dot;
    __syncthreads();

    if (tid < KWIN) {
        float s = (part[0][k]+part[1][k]) * SCALE_ATT
                + logw[((long)b*PP + p)*KWIN + k];
        float m = s;
        #pragma unroll
        for (int o = 16; o > 0; o >>= 1) m = fmaxf(m, __shfl_xor_sync(0xffffffffu, m, o));
        float e = expf(s-m);
        float z = e;
        #pragma unroll
        for (int o = 16; o > 0; o >>= 1) z += __shfl_xor_sync(0xffffffffu, z, o);
        sa[k] = e / z;
    }
    __syncthreads();

    float acc = 0.f;
    #pragma unroll 8
    for (int kk = 0; kk < KWIN; kk++)
        acc = fmaf(sa[kk], base[(long)(sr[kk]+1)*3*DD + 2*DD + h*HDIM + tid], acc);
    attn[((long)b*SS + p+1)*DD + h*HDIM + tid] = tf32r(acc);
}

// ---------------- launcher ----------------
extern "C" void kernel_launch(void* const* d_in, const int* in_sizes, int n_in,
                              void* d_out, int out_size)
{
    const float* x      = (const float*)d_in[0];
    const float* g1     = (const float*)d_in[1];
    const float* b1     = (const float*)d_in[2];
    const float* wq     = (const float*)d_in[3];
    const float* bq     = (const float*)d_in[4];
    const float* wk     = (const float*)d_in[5];
    const float* bk     = (const float*)d_in[6];
    const float* posb   = (const float*)d_in[7];
    const float* w_qkv  = (const float*)d_in[8];
    const float* b_qkv  = (const float*)d_in[9];
    const float* w_proj = (const float*)d_in[10];
    const float* b_proj = (const float*)d_in[11];
    const float* g2     = (const float*)d_in[12];
    const float* b2     = (const float*)d_in[13];
    const float* w_mlp1 = (const float*)d_in[14];
    const float* b_mlp1 = (const float*)d_in[15];
    const float* w_mlp2 = (const float*)d_in[16];
    const float* b_mlp2 = (const float*)d_in[17];
    float* out = (float*)d_out;

    float *xn, *xnr, *q, *k, *scores, *logw, *qkvb, *attn, *x1, *xn2, *hbuf;
    float *rqkv, *rproj, *rm1, *rm2;
    int *routes;
    cudaGetSymbolAddress((void**)&xn,     g_xn);
    cudaGetSymbolAddress((void**)&xnr,    g_xnr);
    cudaGetSymbolAddress((void**)&q,      g_q);
    cudaGetSymbolAddress((void**)&k,      g_k);
    cudaGetSymbolAddress((void**)&scores, g_scores);
    cudaGetSymbolAddress((void**)&routes, g_routes);
    cudaGetSymbolAddress((void**)&logw,   g_logw);
    cudaGetSymbolAddress((void**)&qkvb,   g_qkv);
    cudaGetSymbolAddress((void**)&attn,   g_attn);
    cudaGetSymbolAddress((void**)&x1,     g_x1);
    cudaGetSymbolAddress((void**)&xn2,    g_xn2);
    cudaGetSymbolAddress((void**)&hbuf,   g_h);
    cudaGetSymbolAddress((void**)&rqkv,   g_rqkv);
    cudaGetSymbolAddress((void**)&rproj,  g_rproj);
    cudaGetSymbolAddress((void**)&rm1,    g_rm1);
    cudaGetSymbolAddress((void**)&rm2,    g_rm2);

    // 0. weight preparation (round to tf32 once per call)
    round_tf32_kernel<<<(DD*3*DD+255)/256, 256>>>(w_qkv, rqkv, DD*3*DD);
    round_tf32_kernel<<<(DD*DD+255)/256, 256>>>(w_proj, rproj, DD*DD);
    round_tf32_kernel<<<(DD*MLPD+255)/256, 256>>>(w_mlp1, rm1, DD*MLPD);
    round_tf32_kernel<<<(MLPD*DD+255)/256, 256>>>(w_mlp2, rm2, MLPD*DD);

    // 1. LN1: fp32 out (routing) + tf32-rounded out (QKV gemm)
    ln_kernel<<<NROWS, 256>>>(x, g1, b1, xn, xnr);

    // 2/3. q,k routing projections on xn[:,1:,:]  (fp32 — protects top-k)
    {
        dim3 grid((DD+127)/128, (PP+127)/128, BB);
        sgemm_kernel<0,0><<<grid, 256>>>(xn + DD, wq, q, PP, DD, DD,
                                         (long)SS*DD, 0, (long)PP*DD,
                                         bq, nullptr, 0);
        sgemm_kernel<0,0><<<grid, 256>>>(xn + DD, wk, k, PP, DD, DD,
                                         (long)SS*DD, 0, (long)PP*DD,
                                         bk, nullptr, 0);
    }
    // 4. l2 normalize (fp32)
    l2norm_kernel<<<BB*PP, 256>>>(q);
    l2norm_kernel<<<BB*PP, 256>>>(k);

    // 5. routing scores = q @ k^T (+pos_bias, diag mask, /TEMP)  (fp32)
    {
        dim3 grid((PP+127)/128, (PP+127)/128, BB);
        sgemm_kernel<1,1><<<grid, 256>>>(q, k, scores, PP, PP, DD,
                                         (long)PP*DD, (long)PP*DD, (long)PP*PP,
                                         nullptr, posb, 0);
    }
    // 6. top-32 + log-softmax weights (warp per row)
    topk_warp_kernel<<<BB*PP/8, 256>>>(scores, routes, logw);

    // 7. QKV projection (TF32, pre-rounded operands)
    {
        dim3 grid((3*DD)/TBN, (NROWS+TBM-1)/TBM);
        tf32_nn_kernel<0><<<grid, 256>>>(xnr, rqkv, qkvb, NROWS, 3*DD, DD, DD,
                                         b_qkv, nullptr);
    }
    // 8. CLS attention
    cls_attn_kernel<<<BB*HH, 256>>>(qkvb, attn);
    // 9. patch attention
    patch_attn_kernel<<<BB*HH*PP, 64>>>(qkvb, routes, logw, attn);

    // 10. proj + residual x (TF32)
    {
        dim3 grid(DD/TBN, (NROWS+TBM-1)/TBM);
        tf32_nn_kernel<2><<<grid, 256>>>(attn, rproj, x1, NROWS, DD, DD, DD,
                                         b_proj, x);
    }
    // 11. LN2 (only rounded output needed — feeds MLP1 only)
    ln_kernel<<<NROWS, 256>>>(x1, g2, b2, nullptr, xn2);

    // 12. MLP1 + exact GELU (TF32, output rounded for MLP2)
    {
        dim3 grid(MLPD/TBN, (NROWS+TBM-1)/TBM);
        tf32_nn_kernel<3><<<grid, 256>>>(xn2, rm1, hbuf, NROWS, MLPD, DD, DD,
                                         b_mlp1, nullptr);
    }
    // 13. MLP2 + residual x1 -> out (TF32)
    {
        dim3 grid(DD/TBN, (NROWS+TBM-1)/TBM);
        tf32_nn_kernel<2><<<grid, 256>>>(hbuf, rm2, out, NROWS, DD, MLPD, MLPD,
                                         b_mlp2, x1);
    }
}

// round 5
// speedup vs baseline: 1.9821x; 1.0688x over previous
#include <cuda_runtime.h>
#include <math.h>
#include <stdint.h>

// ---------------- problem constants ----------------
#define BB   8
#define SS   577
#define DD   768
#define HH   12
#define HDIM 64
#define PP   576
#define KWIN 32
#define MLPD 3072
#define NROWS (BB*SS)        // 4616
#define SCALE_ATT 0.125f
#define TEMP_INV  10.0f

#define TBM 128
#define TBN 128
#define TBK 32
#define ASTR 36    // 32+4: frag bank = 4g + t, conflict-free
#define BSTR 136   // 128+8: frag bank = 8t + g, conflict-free

__device__ __forceinline__ uint32_t f2tf32(float x) {
    uint32_t r;
    asm volatile("cvt.rna.tf32.f32 %0, %1;" : "=r"(r) : "f"(x));
    return r;
}
__device__ __forceinline__ float tf32r(float x) {
    return __uint_as_float(f2tf32(x));
}
__device__ __forceinline__ void cp16(void* dst_smem, const void* src, int srcsize) {
    uint32_t d = (uint32_t)__cvta_generic_to_shared(dst_smem);
    asm volatile("cp.async.cg.shared.global [%0], [%1], 16, %2;"
                 :: "r"(d), "l"(src), "r"(srcsize));
}
__device__ __forceinline__ void mma_tf32(float* d, const uint32_t* a, const uint32_t* b) {
    asm volatile(
        "mma.sync.aligned.m16n8k8.row.col.f32.tf32.tf32.f32 "
        "{%0,%1,%2,%3}, {%4,%5,%6,%7}, {%8,%9}, {%0,%1,%2,%3};"
        : "+f"(d[0]), "+f"(d[1]), "+f"(d[2]), "+f"(d[3])
        : "r"(a[0]), "r"(a[1]), "r"(a[2]), "r"(a[3]), "r"(b[0]), "r"(b[1]));
}

// ---------------- scratch (device globals) ----------------
__device__ float g_xn   [(size_t)BB*SS*DD];
__device__ float g_xnr  [(size_t)BB*SS*DD];
__device__ float g_q    [(size_t)BB*PP*DD];
__device__ float g_k    [(size_t)BB*PP*DD];
__device__ float g_scores[(size_t)BB*PP*PP];
__device__ int   g_routes[(size_t)BB*PP*KWIN];
__device__ float g_logw  [(size_t)BB*PP*KWIN];
__device__ float g_qkv  [(size_t)BB*SS*3*DD];
__device__ float g_attn [(size_t)BB*SS*DD];
__device__ float g_x1   [(size_t)BB*SS*DD];
__device__ float g_xn2  [(size_t)BB*SS*DD];
__device__ float g_h    [(size_t)BB*SS*MLPD];
__device__ float g_rqkv [(size_t)DD*3*DD];
__device__ float g_rproj[(size_t)DD*DD];
__device__ float g_rm1  [(size_t)DD*MLPD];
__device__ float g_rm2  [(size_t)MLPD*DD];

// ---------------- elementwise tf32 rounding (float4) ----------------
__global__ __launch_bounds__(256) void round_tf32_kernel(
    const float* __restrict__ src, float* __restrict__ dst, int n)
{
    int i = (blockIdx.x*256 + threadIdx.x)*4;
    if (i < n) {
        float4 v = *reinterpret_cast<const float4*>(src + i);
        v.x = tf32r(v.x); v.y = tf32r(v.y); v.z = tf32r(v.z); v.w = tf32r(v.w);
        *reinterpret_cast<float4*>(dst + i) = v;
    }
}

// ---------------- LayerNorm (optional fp32 + tf32-rounded outputs) --------
__global__ __launch_bounds__(256) void ln_kernel(
    const float* __restrict__ x, const float* __restrict__ g,
    const float* __restrict__ b, float* __restrict__ y,
    float* __restrict__ yr)
{
    int row = blockIdx.x;
    const float* xr = x + (long)row*DD;
    float s = 0.f, sq = 0.f;
    for (int d = threadIdx.x; d < DD; d += 256) {
        float v = xr[d]; s += v; sq += v*v;
    }
    __shared__ float rs[256], rq[256];
    rs[threadIdx.x] = s; rq[threadIdx.x] = sq;
    __syncthreads();
    for (int o = 128; o > 0; o >>= 1) {
        if (threadIdx.x < o) { rs[threadIdx.x] += rs[threadIdx.x+o]; rq[threadIdx.x] += rq[threadIdx.x+o]; }
        __syncthreads();
    }
    __shared__ float mean_s, rstd_s;
    if (threadIdx.x == 0) {
        float mean = rs[0] / (float)DD;
        float var  = rq[0] / (float)DD - mean*mean;
        mean_s = mean;
        rstd_s = rsqrtf(var + 1e-5f);
    }
    __syncthreads();
    float mean = mean_s, rstd = rstd_s;
    float* ybase  = y  ? (y  + (long)row*DD) : nullptr;
    float* yrbase = yr ? (yr + (long)row*DD) : nullptr;
    for (int d = threadIdx.x; d < DD; d += 256) {
        float v = (xr[d]-mean)*rstd*g[d] + b[d];
        if (ybase)  ybase[d]  = v;
        if (yrbase) yrbase[d] = tf32r(v);
    }
}

// ---------------- merged L2 normalize for q and k ----------------
__global__ __launch_bounds__(256) void l2norm2_kernel(
    float* __restrict__ q, float* __restrict__ k)
{
    int row = blockIdx.x;
    float* xr = (row < BB*PP ? q + (long)row*DD : k + (long)(row-BB*PP)*DD);
    float sq = 0.f;
    for (int d = threadIdx.x; d < DD; d += 256) { float v = xr[d]; sq += v*v; }
    __shared__ float rq[256];
    rq[threadIdx.x] = sq;
    __syncthreads();
    for (int o = 128; o > 0; o >>= 1) {
        if (threadIdx.x < o) rq[threadIdx.x] += rq[threadIdx.x+o];
        __syncthreads();
    }
    __shared__ float inv_s;
    if (threadIdx.x == 0) inv_s = 1.0f / fmaxf(sqrtf(rq[0]), 1e-12f);
    __syncthreads();
    float inv = inv_s;
    for (int d = threadIdx.x; d < DD; d += 256) xr[d] *= inv;
}

// ---------------- fp32 SIMT GEMM body ----------------
// EPI: 0 = +bias ; 1 = scores (+pos_bias, diag mask, *1/TEMP)
template<int EPI, int TRANSB>
__device__ __forceinline__ void sgemm_body(
    float (*As)[132], float (*Bs)[132],
    const float* __restrict__ A, const float* __restrict__ Bm,
    float* __restrict__ C, int M, int N, int K,
    const float* __restrict__ bias, const float* __restrict__ Ex,
    int bm, int bn)
{
    const int BK = 16;
    int tid = threadIdx.x;
    int tx = tid & 15, ty = tid >> 4;

    float acc[8][8];
    #pragma unroll
    for (int i = 0; i < 8; i++)
        #pragma unroll
        for (int j = 0; j < 8; j++) acc[i][j] = 0.f;

    int a_r = tid >> 2;
    int a_c = (tid & 3) * 4;
    int b_r = tid >> 5;
    int b_c = (tid & 31) * 4;

    for (int k0 = 0; k0 < K; k0 += BK) {
        #pragma unroll
        for (int pp = 0; pp < 2; pp++) {
            int m = bm + a_r + pp*64;
            float4 v = make_float4(0.f,0.f,0.f,0.f);
            if (m < M) v = *reinterpret_cast<const float4*>(A + (long)m*K + k0 + a_c);
            As[a_c+0][a_r+pp*64] = v.x;
            As[a_c+1][a_r+pp*64] = v.y;
            As[a_c+2][a_r+pp*64] = v.z;
            As[a_c+3][a_r+pp*64] = v.w;
        }
        if (TRANSB) {
            #pragma unroll
            for (int pp = 0; pp < 2; pp++) {
                int n = bn + a_r + pp*64;
                float4 v = make_float4(0.f,0.f,0.f,0.f);
                if (n < N) v = *reinterpret_cast<const float4*>(Bm + (long)n*K + k0 + a_c);
                Bs[a_c+0][a_r+pp*64] = v.x;
                Bs[a_c+1][a_r+pp*64] = v.y;
                Bs[a_c+2][a_r+pp*64] = v.z;
                Bs[a_c+3][a_r+pp*64] = v.w;
            }
        } else {
            #pragma unroll
            for (int pp = 0; pp < 2; pp++) {
                int kk = k0 + b_r + pp*8;
                int n  = bn + b_c;
                float4 v = make_float4(0.f,0.f,0.f,0.f);
                if (n < N) v = *reinterpret_cast<const float4*>(Bm + (long)kk*N + n);
                *reinterpret_cast<float4*>(&Bs[b_r+pp*8][b_c]) = v;
            }
        }
        __syncthreads();

        #pragma unroll
        for (int kk = 0; kk < BK; kk++) {
            float a[8], bfrag[8];
            #pragma unroll
            for (int i = 0; i < 4; i++) {
                a[i]       = As[kk][ty*4+i];
                a[i+4]     = As[kk][64+ty*4+i];
                bfrag[i]   = Bs[kk][tx*4+i];
                bfrag[i+4] = Bs[kk][64+tx*4+i];
            }
            #pragma unroll
            for (int i = 0; i < 8; i++)
                #pragma unroll
                for (int j = 0; j < 8; j++)
                    acc[i][j] = fmaf(a[i], bfrag[j], acc[i][j]);
        }
        __syncthreads();
    }

    #pragma unroll
    for (int i = 0; i < 8; i++) {
        int m = bm + ((i < 4) ? (ty*4+i) : (64+ty*4+(i-4)));
        if (m >= M) continue;
        #pragma unroll
        for (int j = 0; j < 8; j++) {
            int n = bn + ((j < 4) ? (tx*4+j) : (64+tx*4+(j-4)));
            if (n >= N) continue;
            float v = acc[i][j];
            if (EPI == 0) v += bias[n];
            if (EPI == 1) {
                v += Ex[(long)m*N + n];
                if (m == n) v = -1e9f;
                v *= TEMP_INV;
            }
            C[(long)m*N + n] = v;
        }
    }
}

// ---------------- TF32 GEMM body: TBK=32, 2-stage cp.async ----------------
// EPI: 0 = +bias ; 2 = +bias +residual ; 3 = +bias + exact GELU (out rounded)
template<int EPI>
__device__ __forceinline__ void tf32_body(
    float (*As)[TBM][ASTR], float (*Bs)[TBK][BSTR],
    const float* __restrict__ A, const float* __restrict__ B,
    float* __restrict__ C, int M, int N, int K, int lda,
    const float* __restrict__ bias, const float* __restrict__ resid,
    int bm, int bn)
{
    int tid  = threadIdx.x;
    int wid  = tid >> 5, lane = tid & 31;
    int wr   = wid & 1;
    int wc   = wid >> 1;
    int g    = lane >> 2;
    int t    = lane & 3;

    float acc[4][4][4];
    #pragma unroll
    for (int i = 0; i < 4; i++)
        #pragma unroll
        for (int j = 0; j < 4; j++)
            #pragma unroll
            for (int r = 0; r < 4; r++) acc[i][j][r] = 0.f;

    int a_row = tid >> 3;          // 0..31 (4 passes -> 128)
    int a_col = (tid & 7) * 4;     // 0..28
    int b_row = tid >> 5;          // 0..7  (4 passes -> 32)
    int b_col = (tid & 31) * 4;

    auto load_stage = [&](int buf, int k0) {
        #pragma unroll
        for (int pp = 0; pp < 4; pp++) {
            int m = bm + a_row + pp*32;
            cp16(&As[buf][a_row + pp*32][a_col],
                 A + (long)m*lda + k0 + a_col, m < M ? 16 : 0);
        }
        #pragma unroll
        for (int pp = 0; pp < 4; pp++)
            cp16(&Bs[buf][b_row + pp*8][b_col],
                 B + (long)(k0 + b_row + pp*8)*N + bn + b_col, 16);
        asm volatile("cp.async.commit_group;");
    };

    int KT = K / TBK;
    load_stage(0, 0);
    for (int kt = 0; kt < KT; kt++) {
        asm volatile("cp.async.wait_group 0;");
        __syncthreads();                      // data ready + prev buf fully consumed
        if (kt + 1 < KT) load_stage((kt+1)&1, (kt+1)*TBK);
        int buf = kt & 1;

        #pragma unroll
        for (int ka = 0; ka < 4; ka++) {
            int kk = ka*8;
            uint32_t afrag[4][4];
            #pragma unroll
            for (int ma = 0; ma < 4; ma++) {
                int r = wr*64 + ma*16 + g;
                afrag[ma][0] = __float_as_uint(As[buf][r  ][kk + t    ]);
                afrag[ma][1] = __float_as_uint(As[buf][r+8][kk + t    ]);
                afrag[ma][2] = __float_as_uint(As[buf][r  ][kk + t + 4]);
                afrag[ma][3] = __float_as_uint(As[buf][r+8][kk + t + 4]);
            }
            uint32_t bfrag[4][2];
            #pragma unroll
            for (int na = 0; na < 4; na++) {
                int c = wc*32 + na*8 + g;
                bfrag[na][0] = __float_as_uint(Bs[buf][kk + t    ][c]);
                bfrag[na][1] = __float_as_uint(Bs[buf][kk + t + 4][c]);
            }
            #pragma unroll
            for (int ma = 0; ma < 4; ma++)
                #pragma unroll
                for (int na = 0; na < 4; na++)
                    mma_tf32(acc[ma][na], afrag[ma], bfrag[na]);
        }
    }

    #pragma unroll
    for (int ma = 0; ma < 4; ma++) {
        int row0 = bm + wr*64 + ma*16 + g;
        #pragma unroll
        for (int na = 0; na < 4; na++) {
            int col = bn + wc*32 + na*8 + 2*t;
            float b0 = bias[col], b1 = bias[col+1];
            #pragma unroll
            for (int half = 0; half < 2; half++) {
                int row = row0 + half*8;
                if (row >= M) continue;
                float v0 = acc[ma][na][half*2+0] + b0;
                float v1 = acc[ma][na][half*2+1] + b1;
                if (EPI == 2) {
                    v0 += resid[(long)row*N + col];
                    v1 += resid[(long)row*N + col + 1];
                }
                if (EPI == 3) {
                    v0 = 0.5f*v0*(1.0f + erff(v0*0.7071067811865475f));
                    v1 = 0.5f*v1*(1.0f + erff(v1*0.7071067811865475f));
                    v0 = tf32r(v0); v1 = tf32r(v1);   // feeds mlp2 MMA
                }
                *reinterpret_cast<float2*>(C + (long)row*N + col) = make_float2(v0, v1);
            }
        }
    }
}

// shared-memory union for fused / standalone kernels
union GemmSmem {
    struct { float As[2][TBM][ASTR]; float Bs[2][TBK][BSTR]; } t;
    struct { float As[16][132]; float Bs[16][132]; } s;
};

// ---------------- standalone TF32 GEMM ----------------
template<int EPI>
__global__ __launch_bounds__(256, 2) void tf32_nn_kernel(
    const float* __restrict__ A, const float* __restrict__ B,
    float* __restrict__ C, int M, int N, int K, int lda,
    const float* __restrict__ bias, const float* __restrict__ resid)
{
    __shared__ GemmSmem sm;
    tf32_body<EPI>(sm.t.As, sm.t.Bs, A, B, C, M, N, K, lda, bias, resid,
                   blockIdx.y*TBM, blockIdx.x*TBN);
}

// ---------------- standalone fp32 scores GEMM ----------------
__global__ __launch_bounds__(256) void sgemm_scores_kernel(
    const float* __restrict__ Aall, const float* __restrict__ Ball,
    float* __restrict__ Call, const float* __restrict__ posb)
{
    __shared__ float As[16][132];
    __shared__ float Bs[16][132];
    int bz = blockIdx.z;
    sgemm_body<1,1>(As, Bs,
                    Aall + (long)bz*PP*DD, Ball + (long)bz*PP*DD,
                    Call + (long)bz*PP*PP, PP, PP, DD,
                    nullptr, posb, blockIdx.y*128, blockIdx.x*128);
}

// ---------------- fused: QKV (tf32) + q/k routing projections (fp32) -------
#define QKV_NX  (3*DD/TBN)                    // 18
#define QKV_MY  ((NROWS+TBM-1)/TBM)           // 37
#define QKV_BLKS (QKV_NX*QKV_MY)              // 666
#define PROJ_NX (DD/128)                      // 6
#define PROJ_MY ((PP+127)/128)                // 5
#define PROJ_BLKS (PROJ_NX*PROJ_MY*BB)        // 240

__global__ __launch_bounds__(256, 2) void fused_qkv_qkproj_kernel(
    const float* __restrict__ xnr, const float* __restrict__ rqkv,
    const float* __restrict__ b_qkv, float* __restrict__ qkvb,
    const float* __restrict__ xn,
    const float* __restrict__ wq, const float* __restrict__ bq, float* __restrict__ q,
    const float* __restrict__ wk, const float* __restrict__ bk, float* __restrict__ k)
{
    __shared__ GemmSmem sm;
    int bx = blockIdx.x;
    if (bx < QKV_BLKS) {
        int bn = (bx % QKV_NX)*TBN, bm = (bx / QKV_NX)*TBM;
        tf32_body<0>(sm.t.As, sm.t.Bs, xnr, rqkv, qkvb,
                     NROWS, 3*DD, DD, DD, b_qkv, nullptr, bm, bn);
    } else {
        int rel = bx - QKV_BLKS;
        int which = rel / PROJ_BLKS;            // 0 = q, 1 = k
        int idx = rel % PROJ_BLKS;
        int nx = idx % PROJ_NX;
        int my = (idx / PROJ_NX) % PROJ_MY;
        int bz = idx / (PROJ_NX*PROJ_MY);
        const float* A = xn + DD + (long)bz*SS*DD;    // skip CLS row
        const float* W = which ? wk : wq;
        const float* bias = which ? bk : bq;
        float* C = (which ? k : q) + (long)bz*PP*DD;
        sgemm_body<0,0>(sm.s.As, sm.s.Bs, A, W, C, PP, DD, DD,
                        bias, nullptr, my*128, nx*128);
    }
}

// ---------------- warp-per-row top-32 + log-softmax weights ----------------
__global__ __launch_bounds__(256) void topk_warp_kernel(
    const float* __restrict__ scores, int* __restrict__ routes,
    float* __restrict__ logw)
{
    int warp = blockIdx.x*8 + (threadIdx.x >> 5);
    int lane = threadIdx.x & 31;
    const float* srw = scores + (long)warp*PP;
    float v[18];
    #pragma unroll
    for (int j = 0; j < 18; j++) v[j] = srw[j*32 + lane];

    float myTop = 0.f;
    for (int tt = 0; tt < KWIN; tt++) {
        float bv = -INFINITY; int bj = 0;
        #pragma unroll
        for (int j = 0; j < 18; j++)
            if (v[j] > bv) { bv = v[j]; bj = j; }
        int bi = bj*32 + lane;
        #pragma unroll
        for (int o = 16; o > 0; o >>= 1) {
            float ov = __shfl_xor_sync(0xffffffffu, bv, o);
            int   oi = __shfl_xor_sync(0xffffffffu, bi, o);
            if (ov > bv || (ov == bv && oi < bi)) { bv = ov; bi = oi; }
        }
        if (lane == (bi & 31)) v[bi >> 5] = -INFINITY;
        if (lane == tt) myTop = bv;
        if (lane == 0)  routes[(long)warp*KWIN + tt] = bi;
    }
    float m = __shfl_sync(0xffffffffu, myTop, 0);
    float e = expf(myTop - m);
    float z = e;
    #pragma unroll
    for (int o = 16; o > 0; o >>= 1) z += __shfl_xor_sync(0xffffffffu, z, o);
    float lse = m + logf(z);
    logw[(long)warp*KWIN + lane] = fmaxf(myTop - lse, -10.0f);
}

// ---------------- CLS attention ----------------
__global__ __launch_bounds__(256) void cls_attn_kernel(
    const float* __restrict__ qkv, float* __restrict__ attn)
{
    int b = blockIdx.x / HH, h = blockIdx.x % HH;
    const float* base = qkv + (long)b*SS*3*DD;
    int tid = threadIdx.x;
    __shared__ float qv[HDIM];
    __shared__ float sc[SS];
    __shared__ float red[256];
    __shared__ float m_s, z_s;
    if (tid < HDIM) qv[tid] = base[h*HDIM + tid];
    __syncthreads();

    float lmax = -INFINITY;
    for (int k = tid; k < SS; k += 256) {
        const float* kr = base + (long)k*3*DD + DD + h*HDIM;
        float dot = 0.f;
        #pragma unroll
        for (int d = 0; d < HDIM; d++) dot = fmaf(qv[d], kr[d], dot);
        float s = dot * SCALE_ATT;
        sc[k] = s;
        lmax = fmaxf(lmax, s);
    }
    red[tid] = lmax;
    __syncthreads();
    for (int o = 128; o > 0; o >>= 1) {
        if (tid < o) red[tid] = fmaxf(red[tid], red[tid+o]);
        __syncthreads();
    }
    if (tid == 0) m_s = red[0];
    __syncthreads();
    float m = m_s, lsum = 0.f;
    for (int k = tid; k < SS; k += 256) {
        float e = expf(sc[k]-m); sc[k] = e; lsum += e;
    }
    red[tid] = lsum;
    __syncthreads();
    for (int o = 128; o > 0; o >>= 1) {
        if (tid < o) red[tid] += red[tid+o];
        __syncthreads();
    }
    if (tid == 0) z_s = red[0];
    __syncthreads();
    float zinv = 1.0f / z_s;

    int d = tid & 63, part = tid >> 6;
    float acc = 0.f;
    for (int k = part; k < SS; k += 4)
        acc = fmaf(sc[k], base[(long)k*3*DD + 2*DD + h*HDIM + d], acc);
    __shared__ float ro[4][HDIM];
    ro[part][d] = acc;
    __syncthreads();
    if (tid < HDIM)
        attn[((long)b*SS)*DD + h*HDIM + tid] =
            tf32r((ro[0][tid]+ro[1][tid]+ro[2][tid]+ro[3][tid]) * zinv);
}

// ---------------- Patch attention (gathered 32-key windows) ----------------
__global__ __launch_bounds__(64) void patch_attn_kernel(
    const float* __restrict__ qkv, const int* __restrict__ routes,
    const float* __restrict__ logw, float* __restrict__ attn)
{
    int id = blockIdx.x;
    int p = id % PP;
    int h = (id / PP) % HH;
    int b = id / (PP*HH);
    const float* base = qkv + (long)b*SS*3*DD;
    int tid = threadIdx.x;

    __shared__ float qs[HDIM];
    __shared__ int   sr[KWIN];
    __shared__ float sa[KWIN];
    __shared__ float part[2][KWIN];

    qs[tid] = base[(long)(p+1)*3*DD + h*HDIM + tid];
    if (tid < KWIN) sr[tid] = routes[((long)b*PP + p)*KWIN + tid];
    __syncthreads();

    int k = tid & 31, half = tid >> 5;
    const float* kr = base + (long)(sr[k]+1)*3*DD + DD + h*HDIM + half*32;
    float dot = 0.f;
    #pragma unroll
    for (int d = 0; d < 32; d++) dot = fmaf(qs[half*32+d], kr[d], dot);
    part[half][k] = dot;
    __syncthreads();

    if (tid < KWIN) {
        float s = (part[0][k]+part[1][k]) * SCALE_ATT
                + logw[((long)b*PP + p)*KWIN + k];
        float m = s;
        #pragma unroll
        for (int o = 16; o > 0; o >>= 1) m = fmaxf(m, __shfl_xor_sync(0xffffffffu, m, o));
        float e = expf(s-m);
        float z = e;
        #pragma unroll
        for (int o = 16; o > 0; o >>= 1) z += __shfl_xor_sync(0xffffffffu, z, o);
        sa[k] = e / z;
    }
    __syncthreads();

    float acc = 0.f;
    #pragma unroll 8
    for (int kk = 0; kk < KWIN; kk++)
        acc = fmaf(sa[kk], base[(long)(sr[kk]+1)*3*DD + 2*DD + h*HDIM + tid], acc);
    attn[((long)b*SS + p+1)*DD + h*HDIM + tid] = tf32r(acc);
}

// ---------------- launcher ----------------
extern "C" void kernel_launch(void* const* d_in, const int* in_sizes, int n_in,
                              void* d_out, int out_size)
{
    const float* x      = (const float*)d_in[0];
    const float* g1     = (const float*)d_in[1];
    const float* b1     = (const float*)d_in[2];
    const float* wq     = (const float*)d_in[3];
    const float* bq     = (const float*)d_in[4];
    const float* wk     = (const float*)d_in[5];
    const float* bk     = (const float*)d_in[6];
    const float* posb   = (const float*)d_in[7];
    const float* w_qkv  = (const float*)d_in[8];
    const float* b_qkv  = (const float*)d_in[9];
    const float* w_proj = (const float*)d_in[10];
    const float* b_proj = (const float*)d_in[11];
    const float* g2     = (const float*)d_in[12];
    const float* b2     = (const float*)d_in[13];
    const float* w_mlp1 = (const float*)d_in[14];
    const float* b_mlp1 = (const float*)d_in[15];
    const float* w_mlp2 = (const float*)d_in[16];
    const float* b_mlp2 = (const float*)d_in[17];
    float* out = (float*)d_out;

    float *xn, *xnr, *q, *k, *scores, *logw, *qkvb, *attn, *x1, *xn2, *hbuf;
    float *rqkv, *rproj, *rm1, *rm2;
    int *routes;
    cudaGetSymbolAddress((void**)&xn,     g_xn);
    cudaGetSymbolAddress((void**)&xnr,    g_xnr);
    cudaGetSymbolAddress((void**)&q,      g_q);
    cudaGetSymbolAddress((void**)&k,      g_k);
    cudaGetSymbolAddress((void**)&scores, g_scores);
    cudaGetSymbolAddress((void**)&routes, g_routes);
    cudaGetSymbolAddress((void**)&logw,   g_logw);
    cudaGetSymbolAddress((void**)&qkvb,   g_qkv);
    cudaGetSymbolAddress((void**)&attn,   g_attn);
    cudaGetSymbolAddress((void**)&x1,     g_x1);
    cudaGetSymbolAddress((void**)&xn2,    g_xn2);
    cudaGetSymbolAddress((void**)&hbuf,   g_h);
    cudaGetSymbolAddress((void**)&rqkv,   g_rqkv);
    cudaGetSymbolAddress((void**)&rproj,  g_rproj);
    cudaGetSymbolAddress((void**)&rm1,    g_rm1);
    cudaGetSymbolAddress((void**)&rm2,    g_rm2);

    // 0. weight preparation (tf32 rounding, float4)
    round_tf32_kernel<<<(DD*3*DD)/1024, 256>>>(w_qkv, rqkv, DD*3*DD);
    round_tf32_kernel<<<(DD*DD)/1024, 256>>>(w_proj, rproj, DD*DD);
    round_tf32_kernel<<<(DD*MLPD)/1024, 256>>>(w_mlp1, rm1, DD*MLPD);
    round_tf32_kernel<<<(MLPD*DD)/1024, 256>>>(w_mlp2, rm2, MLPD*DD);

    // 1. LN1: fp32 out (routing) + tf32-rounded out (QKV gemm)
    ln_kernel<<<NROWS, 256>>>(x, g1, b1, xn, xnr);

    // 2. FUSED: QKV projection (tf32, tensor pipe) + q/k routing projections
    //    (fp32 SIMT, fma pipe) in one launch — independent work, overlapping pipes
    fused_qkv_qkproj_kernel<<<QKV_BLKS + 2*PROJ_BLKS, 256>>>(
        xnr, rqkv, b_qkv, qkvb, xn, wq, bq, q, wk, bk, k);

    // 3. l2 normalize q and k (one launch)
    l2norm2_kernel<<<2*BB*PP, 256>>>(q, k);

    // 4. routing scores = q @ k^T (+pos_bias, diag mask, /TEMP)  (fp32)
    {
        dim3 grid((PP+127)/128, (PP+127)/128, BB);
        sgemm_scores_kernel<<<grid, 256>>>(q, k, scores, posb);
    }
    // 5. top-32 + log-softmax weights (warp per row)
    topk_warp_kernel<<<BB*PP/8, 256>>>(scores, routes, logw);

    // 6. CLS attention
    cls_attn_kernel<<<BB*HH, 256>>>(qkvb, attn);
    // 7. patch attention
    patch_attn_kernel<<<BB*HH*PP, 64>>>(qkvb, routes, logw, attn);

    // 8. proj + residual x (tf32)
    {
        dim3 grid(DD/TBN, (NROWS+TBM-1)/TBM);
        tf32_nn_kernel<2><<<grid, 256>>>(attn, rproj, x1, NROWS, DD, DD, DD,
                                         b_proj, x);
    }
    // 9. LN2 (rounded output only — feeds MLP1)
    ln_kernel<<<NROWS, 256>>>(x1, g2, b2, nullptr, xn2);

    // 10. MLP1 + exact GELU (tf32, output rounded for MLP2)
    {
        dim3 grid(MLPD/TBN, (NROWS+TBM-1)/TBM);
        tf32_nn_kernel<3><<<grid, 256>>>(xn2, rm1, hbuf, NROWS, MLPD, DD, DD,
                                         b_mlp1, nullptr);
    }
    // 11. MLP2 + residual x1 -> out (tf32)
    {
        dim3 grid(DD/TBN, (NROWS+TBM-1)/TBM);
        tf32_nn_kernel<2><<<grid, 256>>>(hbuf, rm2, out, NROWS, DD, MLPD, MLPD,
                                         b_mlp2, x1);
    }
}